// round 16
// baseline (speedup 1.0000x reference)
#include <cuda_runtime.h>
#include <cuda_fp16.h>
#include <math.h>
#include <stdint.h>

#define B_   2
#define T_   2048
#define DIN  2048
#define DOUT 2048
#define H_   16
#define HD   128

// Scratch (static device globals — no allocation allowed)
__device__ __half g_xh[(size_t)B_ * T_ * DIN];
__device__ __half g_wqh[(size_t)DOUT * DIN];
__device__ __half g_wkh[(size_t)HD * DIN];
__device__ __half g_wvh[(size_t)HD * DIN];
__device__ __half g_woh[(size_t)DOUT * DOUT];
__device__ __half g_Qh[(size_t)B_ * H_ * T_ * HD];   // [b,h,t,d], pre-scaled by log2e/sqrt(hd)
__device__ __half g_Kh[(size_t)B_ * T_ * HD];        // [b,t,d]
__device__ __half g_Vt[(size_t)B_ * HD * T_];        // [b,d,t]  (transposed)
__device__ __half g_Ch[(size_t)B_ * T_ * DOUT];      // ctx fp16

__device__ __forceinline__ uint32_t pack_h2(float a, float b) {
    __half2 h = __floats2half2_rn(a, b);
    return *reinterpret_cast<uint32_t*>(&h);
}

__device__ __forceinline__ uint32_t smem_u32p(const void* p) {
    uint32_t a;
    asm("{ .reg .u64 t; cvta.to.shared.u64 t, %1; cvt.u32.u64 %0, t; }"
        : "=r"(a) : "l"(p));
    return a;
}

__device__ __forceinline__ void mma_f16(float c[4], const uint32_t a[4],
                                        uint32_t b0, uint32_t b1) {
    asm volatile(
        "mma.sync.aligned.m16n8k16.row.col.f32.f16.f16.f32 "
        "{%0,%1,%2,%3}, {%4,%5,%6,%7}, {%8,%9}, {%0,%1,%2,%3};"
        : "+f"(c[0]), "+f"(c[1]), "+f"(c[2]), "+f"(c[3])
        : "r"(a[0]), "r"(a[1]), "r"(a[2]), "r"(a[3]), "r"(b0), "r"(b1));
}

#define LDSM4(r, addr) \
    asm volatile("ldmatrix.sync.aligned.m8n8.x4.shared.b16 {%0,%1,%2,%3}, [%4];" \
        : "=r"((r)[0]), "=r"((r)[1]), "=r"((r)[2]), "=r"((r)[3]) : "r"(addr))

__device__ __forceinline__ void cp16(uint32_t dst, const void* src) {
    asm volatile("cp.async.cg.shared.global [%0], [%1], 16;" :: "r"(dst), "l"(src));
}

// ===========================================================================
// Fused fp32 -> fp16 conversion of all five inputs (one launch)
// ===========================================================================
__global__ void cvt_all(const float4* __restrict__ x,  const float4* __restrict__ wq,
                        const float4* __restrict__ wk, const float4* __restrict__ wv,
                        const float4* __restrict__ wo,
                        uint4* __restrict__ xh,  uint4* __restrict__ wqh,
                        uint4* __restrict__ wkh, uint4* __restrict__ wvh,
                        uint4* __restrict__ woh)
{
    const int n_x  = (B_ * T_ * DIN) / 8;
    const int n_wq = (DOUT * DIN) / 8;
    const int n_wk = (HD * DIN) / 8;
    const int n_wo = (DOUT * DOUT) / 8;
    const int total = n_x + n_wq + 2 * n_wk + n_wo;

    int i  = blockIdx.x * blockDim.x + threadIdx.x;
    int st = gridDim.x * blockDim.x;
    for (; i < total; i += st) {
        const float4* s; uint4* d; int j = i;
        if (j < n_x)                 { s = x;  d = xh;  }
        else if ((j -= n_x)  < n_wq) { s = wq; d = wqh; }
        else if ((j -= n_wq) < n_wk) { s = wk; d = wkh; }
        else if ((j -= n_wk) < n_wk) { s = wv; d = wvh; }
        else { j -= n_wk;              s = wo; d = woh; }
        float4 a = s[2 * j], b = s[2 * j + 1];
        d[j] = make_uint4(pack_h2(a.x, a.y), pack_h2(a.z, a.w),
                          pack_h2(b.x, b.y), pack_h2(b.z, b.w));
    }
}

// ===========================================================================
// fp16 GEMM, cp.async 3-stage, BK=64, ldmatrix fragments (proven config).
// 128x128 CTA tile, 256 threads = 8 warps in 2(M) x 4(N), warp tile 64x32.
// MODE 0: fused QKV (bx<16 Q, 16 K, 17 V-transposed-via-smem)
// MODE 2: output proj (f32 + bias)
// ===========================================================================
#define GSTAGES   3
#define ROWB      144                        // 128B data + 16B pad
#define HALF_STG  18432                      // 128 rows * 144B
#define STG_BYTES (2 * HALF_STG)             // 36864
#define GEMM_SMEM_BYTES (GSTAGES * STG_BYTES)  // 110592
#define VT_PITCH  136                        // halfs: 128 data + 8 pad (272B)

template <int MODE>
__global__ __launch_bounds__(256, 2)
void gemm_cp(const __half* __restrict__ A,  const __half* __restrict__ W0,
             const __half* __restrict__ W1, const __half* __restrict__ W2,
             const float* __restrict__ bias,
             __half* outQ, __half* outK, __half* outVt, float* outF,
             int K)
{
    extern __shared__ __align__(16) uint32_t sm[];

    const int tid  = threadIdx.x;
    const int lane = tid & 31;
    const int warp = tid >> 5;
    const int wm   = warp >> 2;
    const int wn   = warp & 3;
    const int g    = lane >> 2;
    const int t    = lane & 3;
    const int m0   = blockIdx.y << 7;
    const int bx   = blockIdx.x;

    const __half* Wp;
    int n0;
    if (MODE == 0) {
        if (bx < 16)      { Wp = W0; n0 = bx << 7; }
        else if (bx == 16){ Wp = W1; n0 = 0; }
        else              { Wp = W2; n0 = 0; }
    } else {
        Wp = W0; n0 = bx << 7;
    }

    const uint32_t smb = smem_u32p(sm);
    const int nkt = K >> 6;   // BK = 64 fp16

    const int lm = (lane >> 3) & 1;
    const int lq = lane >> 4;
    const int lr = lane & 7;
    const uint32_t aoff = (uint32_t)((wm * 64 + lm * 8 + lr) * ROWB + lq * 16);
    const uint32_t boff = (uint32_t)((wn * 32 + lq * 8 + lr) * ROWB + lm * 16) + HALF_STG;

    auto FILL = [&](int stage, int kt) {
        const int k0 = kt << 6;
        const uint32_t base = smb + stage * STG_BYTES;
        #pragma unroll
        for (int j = 0; j < 4; j++) {
            int c   = tid + j * 256;
            int row = c >> 3;
            int qc  = c & 7;
            cp16(base + row * ROWB + qc * 16,
                 A  + (size_t)(m0 + row) * K + k0 + qc * 8);
            cp16(base + HALF_STG + row * ROWB + qc * 16,
                 Wp + (size_t)(n0 + row) * K + k0 + qc * 8);
        }
        asm volatile("cp.async.commit_group;" ::: "memory");
    };

    FILL(0, 0);
    FILL(1, 1);

    float acc[4][4][4] = {};
    int st = 0;

    for (int kt = 0; kt < nkt; kt++) {
        asm volatile("cp.async.wait_group 1;" ::: "memory");
        __syncthreads();

        const int pf = kt + 2;
        if (pf < nkt) {
            int pst = st + 2; if (pst >= GSTAGES) pst -= GSTAGES;
            FILL(pst, pf);
        }

        const uint32_t Ab = smb + st * STG_BYTES;

        #pragma unroll
        for (int ks = 0; ks < 4; ks++) {
            const uint32_t koff = ks * 32;
            uint32_t af[4][4];
            #pragma unroll
            for (int mt = 0; mt < 4; mt++)
                LDSM4(af[mt], Ab + aoff + mt * (16 * ROWB) + koff);
            #pragma unroll
            for (int p = 0; p < 2; p++) {
                uint32_t bf[4];
                LDSM4(bf, Ab + boff + p * (16 * ROWB) + koff);
                #pragma unroll
                for (int mt = 0; mt < 4; mt++) {
                    mma_f16(acc[mt][2 * p],     af[mt], bf[0], bf[1]);
                    mma_f16(acc[mt][2 * p + 1], af[mt], bf[2], bf[3]);
                }
            }
        }

        if (++st == GSTAGES) st = 0;
    }

    // Q pre-scale: 1/sqrt(128) * log2(e)  (softmax runs in base-2 domain)
    const float qscale = 0.08838834764831845f * 1.4426950408889634f;

    if (MODE == 0 && bx == 17) {
        // V epilogue: transpose through smem, coalesced 16B stores to Vt[b,d,t]
        __syncthreads();
        __half* vs = (__half*)sm;
        const int bb  = m0 >> 11;
        const int tt0 = m0 & (T_ - 1);
        #pragma unroll
        for (int mt = 0; mt < 4; mt++) {
            #pragma unroll
            for (int nt = 0; nt < 4; nt++) {
                int cnl = wn * 32 + nt * 8 + 2 * t;
                #pragma unroll
                for (int half_ = 0; half_ < 2; half_++) {
                    int ttl = wm * 64 + mt * 16 + g + half_ * 8;
                    vs[cnl       * VT_PITCH + ttl] = __float2half_rn(acc[mt][nt][half_ * 2]);
                    vs[(cnl + 1) * VT_PITCH + ttl] = __float2half_rn(acc[mt][nt][half_ * 2 + 1]);
                }
            }
        }
        __syncthreads();
        #pragma unroll
        for (int j = 0; j < 8; j++) {
            int c   = tid + j * 256;
            int row = c >> 4;
            int qc  = c & 15;
            const uint4 v = *(const uint4*)&vs[row * VT_PITCH + qc * 8];
            *(uint4*)&outVt[((size_t)bb * HD + row) * T_ + tt0 + qc * 8] = v;
        }
        return;
    }

    #pragma unroll
    for (int mt = 0; mt < 4; mt++) {
        #pragma unroll
        for (int nt = 0; nt < 4; nt++) {
            int rm = m0 + wm * 64 + mt * 16 + g;
            int cn = n0 + wn * 32 + nt * 8 + 2 * t;
            #pragma unroll
            for (int half_ = 0; half_ < 2; half_++) {
                int m = rm + half_ * 8;
                float v0 = acc[mt][nt][half_ * 2];
                float v1 = acc[mt][nt][half_ * 2 + 1];
                int bb = m >> 11;
                int tt = m & (T_ - 1);
                if (MODE == 0) {
                    if (bx < 16) {
                        int hh = cn >> 7;
                        int d  = cn & (HD - 1);
                        *(uint32_t*)&outQ[(((size_t)(bb * H_ + hh)) * T_ + tt) * HD + d] =
                            pack_h2(v0 * qscale, v1 * qscale);
                    } else {
                        *(uint32_t*)&outK[(size_t)m * HD + cn] = pack_h2(v0, v1);
                    }
                } else {
                    float* dst = &outF[(size_t)m * DOUT + cn];
                    dst[0] = v0 + bias[cn];
                    dst[1] = v1 + bias[cn + 1];
                }
            }
        }
    }
}

// ===========================================================================
// Flash MQA attention: 256 queries/CTA, 8 warps, fp16 mma + ldmatrix,
// fixed-offset base-2 softmax p = exp2(s - 8).
// NOW: 3-buffer K/V ring with cp.async.wait_group 1 — two fills stay in
// flight during each tile's compute (deeper L2-latency hiding).
// ===========================================================================
#define QPITCH 68
#define VPITCH 36
#define QB     (QPITCH * 4)     // 272 bytes
#define VB     (VPITCH * 4)     // 144 bytes
#define NBUF   3

#define QS_U32   0
#define KV_STRIDE (64 * QPITCH + 128 * VPITCH)
#define KS_U32(b) (256 * QPITCH + (b) * KV_STRIDE)
#define VS_U32(b) (KS_U32(b) + 64 * QPITCH)
#define ATTN_SMEM_U32  (256 * QPITCH + NBUF * KV_STRIDE)   // 44288 u32
#define ATTN_SMEM_BYTES (ATTN_SMEM_U32 * 4)                // 177152 B

#define SOFTMAX_OFF 8.0f

__global__ __launch_bounds__(256, 1)
void attn_h(const __half* __restrict__ Qt, const __half* __restrict__ Kd,
            const __half* __restrict__ Vt, __half* __restrict__ Ctx)
{
    extern __shared__ uint32_t smu[];

    const int tid  = threadIdx.x;
    const int lane = tid & 31;
    const int warp = tid >> 5;
    const int g    = lane >> 2;
    const int t    = lane & 3;
    const int b    = blockIdx.z;
    const int h    = blockIdx.y;
    const int q0   = blockIdx.x << 8;

    const unsigned FULL = 0xffffffffu;
    const uint32_t smb = smem_u32p(smu);

    auto ISSUE = [&](int buf, int kt) {
        #pragma unroll
        for (int j = 0; j < 4; j++) {
            int c   = tid + j * 256;
            int row = c >> 4;
            int qc  = c & 15;
            cp16(smb + (KS_U32(buf) + row * QPITCH + qc * 4) * 4,
                 Kd + ((size_t)b * T_ + kt * 64 + row) * HD + qc * 8);
        }
        #pragma unroll
        for (int j = 0; j < 4; j++) {
            int c   = tid + j * 256;
            int row = c >> 3;
            int qc  = c & 7;
            cp16(smb + (VS_U32(buf) + row * VPITCH + qc * 4) * 4,
                 Vt + ((size_t)b * HD + row) * T_ + kt * 64 + qc * 8);
        }
        asm volatile("cp.async.commit_group;" ::: "memory");
    };

    ISSUE(0, 0);
    ISSUE(1, 1);

    const __half* Qbase = Qt + (((size_t)(b * H_ + h)) * T_ + q0) * HD;
    #pragma unroll
    for (int i = 0; i < 16; i++) {
        int idx = tid + i * 256;
        int row = idx >> 4;
        int qc  = idx & 15;
        uint4 v = *(const uint4*)(Qbase + (size_t)row * HD + qc * 8);
        *(uint4*)&smu[QS_U32 + row * QPITCH + qc * 4] = v;
    }

    float o[2][16][4] = {};
    float l_lo[2] = {0.0f, 0.0f};
    float l_hi[2] = {0.0f, 0.0f};

    const int r0 = warp * 32;
    const int NT = T_ / 64;

    const int lm = (lane >> 3) & 1;
    const int lq = lane >> 4;
    const int lr = lane & 7;
    const uint32_t q_off = (uint32_t)((r0 + lm * 8 + lr) * QB + lq * 16);
    const uint32_t k_off = (uint32_t)((lq * 8 + lr) * QB + lm * 16);
    const uint32_t v_off = (uint32_t)((lq * 8 + lr) * VB + lm * 16);

    int cur = 0;
    for (int kt = 0; kt < NT; kt++) {
        asm volatile("cp.async.wait_group 1;" ::: "memory");
        __syncthreads();
        if (kt + 2 < NT) {
            int nb = cur + 2; if (nb >= NBUF) nb -= NBUF;
            ISSUE(nb, kt + 2);
        }

        const uint32_t ksb = smb + KS_U32(cur) * 4;
        const uint32_t vsb = smb + VS_U32(cur) * 4;

        // ---- S = Q K^T
        float s[2][8][4] = {};
        #pragma unroll
        for (int ks = 0; ks < 8; ks++) {
            const uint32_t koff = ks * 32;
            uint32_t af0[4], af1[4];
            LDSM4(af0, smb + q_off + koff);
            LDSM4(af1, smb + q_off + 16 * QB + koff);
            #pragma unroll
            for (int p = 0; p < 4; p++) {
                uint32_t kf[4];
                LDSM4(kf, ksb + k_off + p * (16 * QB) + koff);
                mma_f16(s[0][2 * p],     af0, kf[0], kf[1]);
                mma_f16(s[1][2 * p],     af1, kf[0], kf[1]);
                mma_f16(s[0][2 * p + 1], af0, kf[2], kf[3]);
                mma_f16(s[1][2 * p + 1], af1, kf[2], kf[3]);
            }
        }

        // ---- fixed-offset exp2 + partial row sums
        #pragma unroll
        for (int mt = 0; mt < 2; mt++) {
            #pragma unroll
            for (int nt = 0; nt < 8; nt++) {
                float p0 = exp2f(s[mt][nt][0] - SOFTMAX_OFF);
                float p1 = exp2f(s[mt][nt][1] - SOFTMAX_OFF);
                float p2 = exp2f(s[mt][nt][2] - SOFTMAX_OFF);
                float p3 = exp2f(s[mt][nt][3] - SOFTMAX_OFF);
                l_lo[mt] += p0 + p1;
                l_hi[mt] += p2 + p3;
                s[mt][nt][0] = p0; s[mt][nt][1] = p1;
                s[mt][nt][2] = p2; s[mt][nt][3] = p3;
            }
        }

        // ---- O += P V
        #pragma unroll
        for (int j = 0; j < 4; j++) {
            uint32_t pa[2][4];
            #pragma unroll
            for (int mt = 0; mt < 2; mt++) {
                pa[mt][0] = pack_h2(s[mt][2 * j][0],     s[mt][2 * j][1]);
                pa[mt][1] = pack_h2(s[mt][2 * j][2],     s[mt][2 * j][3]);
                pa[mt][2] = pack_h2(s[mt][2 * j + 1][0], s[mt][2 * j + 1][1]);
                pa[mt][3] = pack_h2(s[mt][2 * j + 1][2], s[mt][2 * j + 1][3]);
            }
            #pragma unroll
            for (int p = 0; p < 8; p++) {
                uint32_t vf[4];
                LDSM4(vf, vsb + v_off + p * (16 * VB) + j * 32);
                mma_f16(o[0][2 * p],     pa[0], vf[0], vf[1]);
                mma_f16(o[1][2 * p],     pa[1], vf[0], vf[1]);
                mma_f16(o[0][2 * p + 1], pa[0], vf[2], vf[3]);
                mma_f16(o[1][2 * p + 1], pa[1], vf[2], vf[3]);
            }
        }

        if (++cur == NBUF) cur = 0;
    }

    // epilogue: quad-reduce l once, normalize, store fp16 ctx
    #pragma unroll
    for (int mt = 0; mt < 2; mt++) {
        float sl = l_lo[mt];
        sl += __shfl_xor_sync(FULL, sl, 1);
        sl += __shfl_xor_sync(FULL, sl, 2);
        float sh = l_hi[mt];
        sh += __shfl_xor_sync(FULL, sh, 1);
        sh += __shfl_xor_sync(FULL, sh, 2);
        const float inv_lo = 1.0f / sl;
        const float inv_hi = 1.0f / sh;
        const int row = q0 + r0 + mt * 16 + g;
        #pragma unroll
        for (int nt = 0; nt < 16; nt++) {
            int col = h * HD + nt * 8 + 2 * t;
            *(uint32_t*)&Ctx[((size_t)b * T_ + row)     * DOUT + col] =
                pack_h2(o[mt][nt][0] * inv_lo, o[mt][nt][1] * inv_lo);
            *(uint32_t*)&Ctx[((size_t)b * T_ + row + 8) * DOUT + col] =
                pack_h2(o[mt][nt][2] * inv_hi, o[mt][nt][3] * inv_hi);
        }
    }
}

// ===========================================================================
extern "C" void kernel_launch(void* const* d_in, const int* in_sizes, int n_in,
                              void* d_out, int out_size)
{
    const float* x  = (const float*)d_in[0];
    const float* Wq = (const float*)d_in[1];
    const float* Wk = (const float*)d_in[2];
    const float* Wv = (const float*)d_in[3];
    const float* Wo = (const float*)d_in[4];
    const float* bo = (const float*)d_in[5];
    float* out = (float*)d_out;

    __half *xh, *wqh, *wkh, *wvh, *woh, *qh, *kh, *vt, *ch;
    cudaGetSymbolAddress((void**)&xh,  g_xh);
    cudaGetSymbolAddress((void**)&wqh, g_wqh);
    cudaGetSymbolAddress((void**)&wkh, g_wkh);
    cudaGetSymbolAddress((void**)&wvh, g_wvh);
    cudaGetSymbolAddress((void**)&woh, g_woh);
    cudaGetSymbolAddress((void**)&qh,  g_Qh);
    cudaGetSymbolAddress((void**)&kh,  g_Kh);
    cudaGetSymbolAddress((void**)&vt,  g_Vt);
    cudaGetSymbolAddress((void**)&ch,  g_Ch);

    cudaFuncSetAttribute(attn_h, cudaFuncAttributeMaxDynamicSharedMemorySize,
                         ATTN_SMEM_BYTES);
    cudaFuncSetAttribute(gemm_cp<0>, cudaFuncAttributeMaxDynamicSharedMemorySize,
                         GEMM_SMEM_BYTES);
    cudaFuncSetAttribute(gemm_cp<2>, cudaFuncAttributeMaxDynamicSharedMemorySize,
                         GEMM_SMEM_BYTES);

    const int M = B_ * T_;

    cvt_all<<<2048, 256>>>((const float4*)x, (const float4*)Wq, (const float4*)Wk,
                           (const float4*)Wv, (const float4*)Wo,
                           (uint4*)xh, (uint4*)wqh, (uint4*)wkh, (uint4*)wvh, (uint4*)woh);

    // fused Q+K+V projections (grid.x: 0..15 Q tiles, 16 K, 17 V-transposed)
    gemm_cp<0><<<dim3(18, M / 128), 256, GEMM_SMEM_BYTES>>>(
        xh, wqh, wkh, wvh, nullptr, qh, kh, vt, nullptr, DIN);

    // attention (256 queries per CTA, 3-buffer K/V ring)
    attn_h<<<dim3(T_ / 256, H_, B_), 256, ATTN_SMEM_BYTES>>>(qh, kh, vt, ch);

    // output projection + bias (f32 out)
    gemm_cp<2><<<dim3(DOUT / 128, M / 128), 256, GEMM_SMEM_BYTES>>>(
        ch, woh, nullptr, nullptr, bo, nullptr, nullptr, nullptr, out, DOUT);
}

// round 17
// speedup vs baseline: 1.0008x; 1.0008x over previous
#include <cuda_runtime.h>
#include <cuda_fp16.h>
#include <math.h>
#include <stdint.h>

#define B_   2
#define T_   2048
#define DIN  2048
#define DOUT 2048
#define H_   16
#define HD   128

// Scratch (static device globals — no allocation allowed)
__device__ __half g_xh[(size_t)B_ * T_ * DIN];
__device__ __half g_wqh[(size_t)DOUT * DIN];
__device__ __half g_wkh[(size_t)HD * DIN];
__device__ __half g_wvh[(size_t)HD * DIN];
__device__ __half g_woh[(size_t)DOUT * DOUT];
__device__ __half g_Qh[(size_t)B_ * H_ * T_ * HD];   // [b,h,t,d], pre-scaled by log2e/sqrt(hd)
__device__ __half g_Kh[(size_t)B_ * T_ * HD];        // [b,t,d]
__device__ __half g_Vt[(size_t)B_ * HD * T_];        // [b,d,t]  (transposed)
__device__ __half g_Ch[(size_t)B_ * T_ * DOUT];      // ctx fp16

__device__ __forceinline__ uint32_t pack_h2(float a, float b) {
    __half2 h = __floats2half2_rn(a, b);
    return *reinterpret_cast<uint32_t*>(&h);
}

__device__ __forceinline__ uint32_t smem_u32p(const void* p) {
    uint32_t a;
    asm("{ .reg .u64 t; cvta.to.shared.u64 t, %1; cvt.u32.u64 %0, t; }"
        : "=r"(a) : "l"(p));
    return a;
}

__device__ __forceinline__ void mma_f16(float c[4], const uint32_t a[4],
                                        uint32_t b0, uint32_t b1) {
    asm volatile(
        "mma.sync.aligned.m16n8k16.row.col.f32.f16.f16.f32 "
        "{%0,%1,%2,%3}, {%4,%5,%6,%7}, {%8,%9}, {%0,%1,%2,%3};"
        : "+f"(c[0]), "+f"(c[1]), "+f"(c[2]), "+f"(c[3])
        : "r"(a[0]), "r"(a[1]), "r"(a[2]), "r"(a[3]), "r"(b0), "r"(b1));
}

#define LDSM4(r, addr) \
    asm volatile("ldmatrix.sync.aligned.m8n8.x4.shared.b16 {%0,%1,%2,%3}, [%4];" \
        : "=r"((r)[0]), "=r"((r)[1]), "=r"((r)[2]), "=r"((r)[3]) : "r"(addr))

__device__ __forceinline__ void cp16(uint32_t dst, const void* src) {
    asm volatile("cp.async.cg.shared.global [%0], [%1], 16;" :: "r"(dst), "l"(src));
}

// ===========================================================================
// Fused fp32 -> fp16 conversion of all five inputs (one launch)
// ===========================================================================
__global__ void cvt_all(const float4* __restrict__ x,  const float4* __restrict__ wq,
                        const float4* __restrict__ wk, const float4* __restrict__ wv,
                        const float4* __restrict__ wo,
                        uint4* __restrict__ xh,  uint4* __restrict__ wqh,
                        uint4* __restrict__ wkh, uint4* __restrict__ wvh,
                        uint4* __restrict__ woh)
{
    const int n_x  = (B_ * T_ * DIN) / 8;
    const int n_wq = (DOUT * DIN) / 8;
    const int n_wk = (HD * DIN) / 8;
    const int n_wo = (DOUT * DOUT) / 8;
    const int total = n_x + n_wq + 2 * n_wk + n_wo;

    int i  = blockIdx.x * blockDim.x + threadIdx.x;
    int st = gridDim.x * blockDim.x;
    for (; i < total; i += st) {
        const float4* s; uint4* d; int j = i;
        if (j < n_x)                 { s = x;  d = xh;  }
        else if ((j -= n_x)  < n_wq) { s = wq; d = wqh; }
        else if ((j -= n_wq) < n_wk) { s = wk; d = wkh; }
        else if ((j -= n_wk) < n_wk) { s = wv; d = wvh; }
        else { j -= n_wk;              s = wo; d = woh; }
        float4 a = s[2 * j], b = s[2 * j + 1];
        d[j] = make_uint4(pack_h2(a.x, a.y), pack_h2(a.z, a.w),
                          pack_h2(b.x, b.y), pack_h2(b.z, b.w));
    }
}

// ===========================================================================
// fp16 GEMM, cp.async 3-stage, BK=64, ldmatrix fragments (proven config).
// 128x128 CTA tile, 256 threads = 8 warps in 2(M) x 4(N), warp tile 64x32.
// MODE 0: fused QKV (bx<16 Q, 16 K, 17 V-transposed-via-smem)
// MODE 2: output proj (f32 + bias)
// ===========================================================================
#define GSTAGES   3
#define ROWB      144                        // 128B data + 16B pad
#define HALF_STG  18432                      // 128 rows * 144B
#define STG_BYTES (2 * HALF_STG)             // 36864
#define GEMM_SMEM_BYTES (GSTAGES * STG_BYTES)  // 110592
#define VT_PITCH  136                        // halfs: 128 data + 8 pad (272B)

template <int MODE>
__global__ __launch_bounds__(256, 2)
void gemm_cp(const __half* __restrict__ A,  const __half* __restrict__ W0,
             const __half* __restrict__ W1, const __half* __restrict__ W2,
             const float* __restrict__ bias,
             __half* outQ, __half* outK, __half* outVt, float* outF,
             int K)
{
    extern __shared__ __align__(16) uint32_t sm[];

    const int tid  = threadIdx.x;
    const int lane = tid & 31;
    const int warp = tid >> 5;
    const int wm   = warp >> 2;
    const int wn   = warp & 3;
    const int g    = lane >> 2;
    const int t    = lane & 3;
    const int m0   = blockIdx.y << 7;
    const int bx   = blockIdx.x;

    const __half* Wp;
    int n0;
    if (MODE == 0) {
        if (bx < 16)      { Wp = W0; n0 = bx << 7; }
        else if (bx == 16){ Wp = W1; n0 = 0; }
        else              { Wp = W2; n0 = 0; }
    } else {
        Wp = W0; n0 = bx << 7;
    }

    const uint32_t smb = smem_u32p(sm);
    const int nkt = K >> 6;   // BK = 64 fp16

    const int lm = (lane >> 3) & 1;
    const int lq = lane >> 4;
    const int lr = lane & 7;
    const uint32_t aoff = (uint32_t)((wm * 64 + lm * 8 + lr) * ROWB + lq * 16);
    const uint32_t boff = (uint32_t)((wn * 32 + lq * 8 + lr) * ROWB + lm * 16) + HALF_STG;

    auto FILL = [&](int stage, int kt) {
        const int k0 = kt << 6;
        const uint32_t base = smb + stage * STG_BYTES;
        #pragma unroll
        for (int j = 0; j < 4; j++) {
            int c   = tid + j * 256;
            int row = c >> 3;
            int qc  = c & 7;
            cp16(base + row * ROWB + qc * 16,
                 A  + (size_t)(m0 + row) * K + k0 + qc * 8);
            cp16(base + HALF_STG + row * ROWB + qc * 16,
                 Wp + (size_t)(n0 + row) * K + k0 + qc * 8);
        }
        asm volatile("cp.async.commit_group;" ::: "memory");
    };

    FILL(0, 0);
    FILL(1, 1);

    float acc[4][4][4] = {};
    int st = 0;

    for (int kt = 0; kt < nkt; kt++) {
        asm volatile("cp.async.wait_group 1;" ::: "memory");
        __syncthreads();

        const int pf = kt + 2;
        if (pf < nkt) {
            int pst = st + 2; if (pst >= GSTAGES) pst -= GSTAGES;
            FILL(pst, pf);
        }

        const uint32_t Ab = smb + st * STG_BYTES;

        #pragma unroll
        for (int ks = 0; ks < 4; ks++) {
            const uint32_t koff = ks * 32;
            uint32_t af[4][4];
            #pragma unroll
            for (int mt = 0; mt < 4; mt++)
                LDSM4(af[mt], Ab + aoff + mt * (16 * ROWB) + koff);
            #pragma unroll
            for (int p = 0; p < 2; p++) {
                uint32_t bf[4];
                LDSM4(bf, Ab + boff + p * (16 * ROWB) + koff);
                #pragma unroll
                for (int mt = 0; mt < 4; mt++) {
                    mma_f16(acc[mt][2 * p],     af[mt], bf[0], bf[1]);
                    mma_f16(acc[mt][2 * p + 1], af[mt], bf[2], bf[3]);
                }
            }
        }

        if (++st == GSTAGES) st = 0;
    }

    // Q pre-scale: 1/sqrt(128) * log2(e)  (softmax runs in base-2 domain)
    const float qscale = 0.08838834764831845f * 1.4426950408889634f;

    if (MODE == 0 && bx == 17) {
        // V epilogue: transpose through smem, coalesced 16B stores to Vt[b,d,t]
        __syncthreads();
        __half* vs = (__half*)sm;
        const int bb  = m0 >> 11;
        const int tt0 = m0 & (T_ - 1);
        #pragma unroll
        for (int mt = 0; mt < 4; mt++) {
            #pragma unroll
            for (int nt = 0; nt < 4; nt++) {
                int cnl = wn * 32 + nt * 8 + 2 * t;
                #pragma unroll
                for (int half_ = 0; half_ < 2; half_++) {
                    int ttl = wm * 64 + mt * 16 + g + half_ * 8;
                    vs[cnl       * VT_PITCH + ttl] = __float2half_rn(acc[mt][nt][half_ * 2]);
                    vs[(cnl + 1) * VT_PITCH + ttl] = __float2half_rn(acc[mt][nt][half_ * 2 + 1]);
                }
            }
        }
        __syncthreads();
        #pragma unroll
        for (int j = 0; j < 8; j++) {
            int c   = tid + j * 256;
            int row = c >> 4;
            int qc  = c & 15;
            const uint4 v = *(const uint4*)&vs[row * VT_PITCH + qc * 8];
            *(uint4*)&outVt[((size_t)bb * HD + row) * T_ + tt0 + qc * 8] = v;
        }
        return;
    }

    #pragma unroll
    for (int mt = 0; mt < 4; mt++) {
        #pragma unroll
        for (int nt = 0; nt < 4; nt++) {
            int rm = m0 + wm * 64 + mt * 16 + g;
            int cn = n0 + wn * 32 + nt * 8 + 2 * t;
            #pragma unroll
            for (int half_ = 0; half_ < 2; half_++) {
                int m = rm + half_ * 8;
                float v0 = acc[mt][nt][half_ * 2];
                float v1 = acc[mt][nt][half_ * 2 + 1];
                int bb = m >> 11;
                int tt = m & (T_ - 1);
                if (MODE == 0) {
                    if (bx < 16) {
                        int hh = cn >> 7;
                        int d  = cn & (HD - 1);
                        *(uint32_t*)&outQ[(((size_t)(bb * H_ + hh)) * T_ + tt) * HD + d] =
                            pack_h2(v0 * qscale, v1 * qscale);
                    } else {
                        *(uint32_t*)&outK[(size_t)m * HD + cn] = pack_h2(v0, v1);
                    }
                } else {
                    float* dst = &outF[(size_t)m * DOUT + cn];
                    dst[0] = v0 + bias[cn];
                    dst[1] = v1 + bias[cn + 1];
                }
            }
        }
    }
}

// ===========================================================================
// Flash MQA attention: 256 queries/CTA, 8 warps, fp16 mma + ldmatrix,
// fixed-offset base-2 softmax p = exp2(s - 8).
// NOW: 3-buffer K/V ring with cp.async.wait_group 1 — two fills stay in
// flight during each tile's compute (deeper L2-latency hiding).
// ===========================================================================
#define QPITCH 68
#define VPITCH 36
#define QB     (QPITCH * 4)     // 272 bytes
#define VB     (VPITCH * 4)     // 144 bytes
#define NBUF   3

#define QS_U32   0
#define KV_STRIDE (64 * QPITCH + 128 * VPITCH)
#define KS_U32(b) (256 * QPITCH + (b) * KV_STRIDE)
#define VS_U32(b) (KS_U32(b) + 64 * QPITCH)
#define ATTN_SMEM_U32  (256 * QPITCH + NBUF * KV_STRIDE)   // 44288 u32
#define ATTN_SMEM_BYTES (ATTN_SMEM_U32 * 4)                // 177152 B

#define SOFTMAX_OFF 8.0f

__global__ __launch_bounds__(256, 1)
void attn_h(const __half* __restrict__ Qt, const __half* __restrict__ Kd,
            const __half* __restrict__ Vt, __half* __restrict__ Ctx)
{
    extern __shared__ uint32_t smu[];

    const int tid  = threadIdx.x;
    const int lane = tid & 31;
    const int warp = tid >> 5;
    const int g    = lane >> 2;
    const int t    = lane & 3;
    const int b    = blockIdx.z;
    const int h    = blockIdx.y;
    const int q0   = blockIdx.x << 8;

    const unsigned FULL = 0xffffffffu;
    const uint32_t smb = smem_u32p(smu);

    auto ISSUE = [&](int buf, int kt) {
        #pragma unroll
        for (int j = 0; j < 4; j++) {
            int c   = tid + j * 256;
            int row = c >> 4;
            int qc  = c & 15;
            cp16(smb + (KS_U32(buf) + row * QPITCH + qc * 4) * 4,
                 Kd + ((size_t)b * T_ + kt * 64 + row) * HD + qc * 8);
        }
        #pragma unroll
        for (int j = 0; j < 4; j++) {
            int c   = tid + j * 256;
            int row = c >> 3;
            int qc  = c & 7;
            cp16(smb + (VS_U32(buf) + row * VPITCH + qc * 4) * 4,
                 Vt + ((size_t)b * HD + row) * T_ + kt * 64 + qc * 8);
        }
        asm volatile("cp.async.commit_group;" ::: "memory");
    };

    ISSUE(0, 0);
    ISSUE(1, 1);

    const __half* Qbase = Qt + (((size_t)(b * H_ + h)) * T_ + q0) * HD;
    #pragma unroll
    for (int i = 0; i < 16; i++) {
        int idx = tid + i * 256;
        int row = idx >> 4;
        int qc  = idx & 15;
        uint4 v = *(const uint4*)(Qbase + (size_t)row * HD + qc * 8);
        *(uint4*)&smu[QS_U32 + row * QPITCH + qc * 4] = v;
    }

    float o[2][16][4] = {};
    float l_lo[2] = {0.0f, 0.0f};
    float l_hi[2] = {0.0f, 0.0f};

    const int r0 = warp * 32;
    const int NT = T_ / 64;

    const int lm = (lane >> 3) & 1;
    const int lq = lane >> 4;
    const int lr = lane & 7;
    const uint32_t q_off = (uint32_t)((r0 + lm * 8 + lr) * QB + lq * 16);
    const uint32_t k_off = (uint32_t)((lq * 8 + lr) * QB + lm * 16);
    const uint32_t v_off = (uint32_t)((lq * 8 + lr) * VB + lm * 16);

    int cur = 0;
    for (int kt = 0; kt < NT; kt++) {
        asm volatile("cp.async.wait_group 1;" ::: "memory");
        __syncthreads();
        if (kt + 2 < NT) {
            int nb = cur + 2; if (nb >= NBUF) nb -= NBUF;
            ISSUE(nb, kt + 2);
        }

        const uint32_t ksb = smb + KS_U32(cur) * 4;
        const uint32_t vsb = smb + VS_U32(cur) * 4;

        // ---- S = Q K^T
        float s[2][8][4] = {};
        #pragma unroll
        for (int ks = 0; ks < 8; ks++) {
            const uint32_t koff = ks * 32;
            uint32_t af0[4], af1[4];
            LDSM4(af0, smb + q_off + koff);
            LDSM4(af1, smb + q_off + 16 * QB + koff);
            #pragma unroll
            for (int p = 0; p < 4; p++) {
                uint32_t kf[4];
                LDSM4(kf, ksb + k_off + p * (16 * QB) + koff);
                mma_f16(s[0][2 * p],     af0, kf[0], kf[1]);
                mma_f16(s[1][2 * p],     af1, kf[0], kf[1]);
                mma_f16(s[0][2 * p + 1], af0, kf[2], kf[3]);
                mma_f16(s[1][2 * p + 1], af1, kf[2], kf[3]);
            }
        }

        // ---- fixed-offset exp2 + partial row sums
        #pragma unroll
        for (int mt = 0; mt < 2; mt++) {
            #pragma unroll
            for (int nt = 0; nt < 8; nt++) {
                float p0 = exp2f(s[mt][nt][0] - SOFTMAX_OFF);
                float p1 = exp2f(s[mt][nt][1] - SOFTMAX_OFF);
                float p2 = exp2f(s[mt][nt][2] - SOFTMAX_OFF);
                float p3 = exp2f(s[mt][nt][3] - SOFTMAX_OFF);
                l_lo[mt] += p0 + p1;
                l_hi[mt] += p2 + p3;
                s[mt][nt][0] = p0; s[mt][nt][1] = p1;
                s[mt][nt][2] = p2; s[mt][nt][3] = p3;
            }
        }

        // ---- O += P V
        #pragma unroll
        for (int j = 0; j < 4; j++) {
            uint32_t pa[2][4];
            #pragma unroll
            for (int mt = 0; mt < 2; mt++) {
                pa[mt][0] = pack_h2(s[mt][2 * j][0],     s[mt][2 * j][1]);
                pa[mt][1] = pack_h2(s[mt][2 * j][2],     s[mt][2 * j][3]);
                pa[mt][2] = pack_h2(s[mt][2 * j + 1][0], s[mt][2 * j + 1][1]);
                pa[mt][3] = pack_h2(s[mt][2 * j + 1][2], s[mt][2 * j + 1][3]);
            }
            #pragma unroll
            for (int p = 0; p < 8; p++) {
                uint32_t vf[4];
                LDSM4(vf, vsb + v_off + p * (16 * VB) + j * 32);
                mma_f16(o[0][2 * p],     pa[0], vf[0], vf[1]);
                mma_f16(o[1][2 * p],     pa[1], vf[0], vf[1]);
                mma_f16(o[0][2 * p + 1], pa[0], vf[2], vf[3]);
                mma_f16(o[1][2 * p + 1], pa[1], vf[2], vf[3]);
            }
        }

        if (++cur == NBUF) cur = 0;
    }

    // epilogue: quad-reduce l once, normalize, store fp16 ctx
    #pragma unroll
    for (int mt = 0; mt < 2; mt++) {
        float sl = l_lo[mt];
        sl += __shfl_xor_sync(FULL, sl, 1);
        sl += __shfl_xor_sync(FULL, sl, 2);
        float sh = l_hi[mt];
        sh += __shfl_xor_sync(FULL, sh, 1);
        sh += __shfl_xor_sync(FULL, sh, 2);
        const float inv_lo = 1.0f / sl;
        const float inv_hi = 1.0f / sh;
        const int row = q0 + r0 + mt * 16 + g;
        #pragma unroll
        for (int nt = 0; nt < 16; nt++) {
            int col = h * HD + nt * 8 + 2 * t;
            *(uint32_t*)&Ctx[((size_t)b * T_ + row)     * DOUT + col] =
                pack_h2(o[mt][nt][0] * inv_lo, o[mt][nt][1] * inv_lo);
            *(uint32_t*)&Ctx[((size_t)b * T_ + row + 8) * DOUT + col] =
                pack_h2(o[mt][nt][2] * inv_hi, o[mt][nt][3] * inv_hi);
        }
    }
}

// ===========================================================================
extern "C" void kernel_launch(void* const* d_in, const int* in_sizes, int n_in,
                              void* d_out, int out_size)
{
    const float* x  = (const float*)d_in[0];
    const float* Wq = (const float*)d_in[1];
    const float* Wk = (const float*)d_in[2];
    const float* Wv = (const float*)d_in[3];
    const float* Wo = (const float*)d_in[4];
    const float* bo = (const float*)d_in[5];
    float* out = (float*)d_out;

    __half *xh, *wqh, *wkh, *wvh, *woh, *qh, *kh, *vt, *ch;
    cudaGetSymbolAddress((void**)&xh,  g_xh);
    cudaGetSymbolAddress((void**)&wqh, g_wqh);
    cudaGetSymbolAddress((void**)&wkh, g_wkh);
    cudaGetSymbolAddress((void**)&wvh, g_wvh);
    cudaGetSymbolAddress((void**)&woh, g_woh);
    cudaGetSymbolAddress((void**)&qh,  g_Qh);
    cudaGetSymbolAddress((void**)&kh,  g_Kh);
    cudaGetSymbolAddress((void**)&vt,  g_Vt);
    cudaGetSymbolAddress((void**)&ch,  g_Ch);

    cudaFuncSetAttribute(attn_h, cudaFuncAttributeMaxDynamicSharedMemorySize,
                         ATTN_SMEM_BYTES);
    cudaFuncSetAttribute(gemm_cp<0>, cudaFuncAttributeMaxDynamicSharedMemorySize,
                         GEMM_SMEM_BYTES);
    cudaFuncSetAttribute(gemm_cp<2>, cudaFuncAttributeMaxDynamicSharedMemorySize,
                         GEMM_SMEM_BYTES);

    const int M = B_ * T_;

    cvt_all<<<2048, 256>>>((const float4*)x, (const float4*)Wq, (const float4*)Wk,
                           (const float4*)Wv, (const float4*)Wo,
                           (uint4*)xh, (uint4*)wqh, (uint4*)wkh, (uint4*)wvh, (uint4*)woh);

    // fused Q+K+V projections (grid.x: 0..15 Q tiles, 16 K, 17 V-transposed)
    gemm_cp<0><<<dim3(18, M / 128), 256, GEMM_SMEM_BYTES>>>(
        xh, wqh, wkh, wvh, nullptr, qh, kh, vt, nullptr, DIN);

    // attention (256 queries per CTA, 3-buffer K/V ring)
    attn_h<<<dim3(T_ / 256, H_, B_), 256, ATTN_SMEM_BYTES>>>(qh, kh, vt, ch);

    // output projection + bias (f32 out)
    gemm_cp<2><<<dim3(DOUT / 128, M / 128), 256, GEMM_SMEM_BYTES>>>(
        ch, woh, nullptr, nullptr, bo, nullptr, nullptr, nullptr, out, DOUT);
}